// round 10
// baseline (speedup 1.0000x reference)
#include <cuda_runtime.h>
#include <cstdint>

// Conv2d N=32, CIN=3, H=W=224, COUT=64, 3x3, s1, p1, fp32.
// Implicit GEMM via mma.sync.m16n8k16 bf16->f32, 3-pass hi/lo fp32 emulation.
// R10 = R9 + register diet for occupancy: BL (lo-weight) fragments live in a
// warp-invariant smem table (reloaded via conflict-free LDS.64 per iter),
// valid/bias predicates inlined; __launch_bounds__(128,4) -> 16 warps/SM.

#define NN 32
#define HWDIM 224
#define IMG (HWDIM*HWDIM)        // 50176
#define COUT 64
#define CIN 3
#define NTHREADS 128
#define PX_PER_BLOCK 512
#define ITERS 8
#define BLKS_PER_IMG (IMG/PX_PER_BLOCK)   // 98

__device__ __forceinline__ uint32_t cvt_bf16x2(float hi, float lo) {
    uint32_t d;
    asm("cvt.rn.bf16x2.f32 %0, %1, %2;" : "=r"(d) : "f"(hi), "f"(lo));
    return d;
}
__device__ __forceinline__ void mma_bf16(float* d, const uint32_t* a, const uint32_t* b) {
    asm volatile(
        "mma.sync.aligned.m16n8k16.row.col.f32.bf16.bf16.f32 "
        "{%0,%1,%2,%3}, {%4,%5,%6,%7}, {%8,%9}, {%0,%1,%2,%3};"
        : "+f"(d[0]), "+f"(d[1]), "+f"(d[2]), "+f"(d[3])
        : "r"(a[0]), "r"(a[1]), "r"(a[2]), "r"(a[3]), "r"(b[0]), "r"(b[1]));
}

// Gather 8 taps for adjacent pixel pair (p0, p0+1); p0 even -> same image row.
__device__ __forceinline__ void gather_taps(
    const float* __restrict__ in_n, int p0, int c,
    const int* coff, const int* dy, const int* dx,
    float* v0, float* v1)
{
    const int y  = p0 / HWDIM;
    const int x0 = p0 % HWDIM;
    const int offs[8] = {0, 1, 8, 9, 16, 17, 24, 25};
#pragma unroll
    for (int t = 0; t < 8; ++t) {
        const int  k     = c + offs[t];
        const bool valid = (k < 27);
        const int  yy    = y + dy[t];
        const bool rowok = valid && ((unsigned)yy < (unsigned)HWDIM);
        const float* rp  = in_n + coff[t] + yy * HWDIM;
        const int  xx0   = x0 + dx[t];
        const bool ok0   = rowok && ((unsigned)xx0 < (unsigned)HWDIM);
        const bool ok1   = rowok && ((unsigned)(xx0 + 1) < (unsigned)HWDIM);
        const float dflt = (k == 27) ? 1.f : 0.f;  // bias tap; 0 otherwise
        v0[t] = ok0 ? __ldg(rp + xx0)     : dflt;
        v1[t] = ok1 ? __ldg(rp + xx0 + 1) : dflt;
    }
}

__global__ __launch_bounds__(NTHREADS, 4)
void conv_mma(const float* __restrict__ xin, const float* __restrict__ wgt,
              const float* __restrict__ bias, float* __restrict__ out)
{
    __shared__ uint2 s_bl[16 * 32];   // BL fragments: [(nt*2+s)*32 + lane], 4KB

    const int tid  = threadIdx.x;
    const int warp = tid >> 5;
    const int lane = tid & 31;
    const int lg   = lane >> 2;     // 0..7
    const int c    = (lane & 3) * 2;

    const int n   = blockIdx.x / BLKS_PER_IMG;
    const int blk = blockIdx.x % BLKS_PER_IMG;
    const float* in_n  = xin + (size_t)n * (CIN * IMG);
    float*       out_n = out + (size_t)n * (COUT * IMG);

    // ---- B fragments: BH in regs; BL to smem (warp-invariant, warp 0 writes) ----
    uint32_t BH[8][2][2];
#pragma unroll
    for (int nt = 0; nt < 8; ++nt) {
        const int co = nt * 8 + lg;
#pragma unroll
        for (int s = 0; s < 2; ++s) {
            uint32_t blr[2];
#pragma unroll
            for (int r = 0; r < 2; ++r) {
                const int k0 = 16 * s + c + 8 * r;
                const int k1 = k0 + 1;
                const float f0 = (k0 < 27) ? wgt[co * 27 + k0] : (k0 == 27 ? bias[co] : 0.f);
                const float f1 = (k1 < 27) ? wgt[co * 27 + k1] : (k1 == 27 ? bias[co] : 0.f);
                const uint32_t h = cvt_bf16x2(f1, f0);
                const float l0 = f0 - __uint_as_float(h << 16);
                const float l1 = f1 - __uint_as_float(h & 0xffff0000u);
                BH[nt][s][r] = h;
                blr[r] = cvt_bf16x2(l1, l0);
            }
            if (warp == 0)
                s_bl[(nt * 2 + s) * 32 + lane] = make_uint2(blr[0], blr[1]);
        }
    }

    // ---- tap descriptors: k = c + offs[t] ----
    const int offs[8] = {0, 1, 8, 9, 16, 17, 24, 25};
    int coff[8], dy[8], dx[8];
#pragma unroll
    for (int t = 0; t < 8; ++t) {
        const int k  = c + offs[t];
        const int kk = (k < 27) ? k : 0;
        const int ci = kk / 9, r = kk % 9;
        coff[t] = ci * IMG;
        dy[t]   = r / 3 - 1;
        dx[t]   = r % 3 - 1;
    }

    __syncthreads();   // BL table ready

    // A row lg -> pixel pbase (even), row lg+8 -> pixel pbase+1.
    const int pbase = blk * PX_PER_BLOCK + warp * 16 + 2 * lg;

    // ---- prologue: gather iteration 0 ----
    float v0[8], v1[8];
    gather_taps(in_n, pbase, c, coff, dy, dx, v0, v1);

    for (int it = 0; it < ITERS; ++it) {
        // ---- split hi/lo, pack A fragments (v0/v1 die here) ----
        uint32_t AH[2][4], AL[2][4];
#pragma unroll
        for (int s = 0; s < 2; ++s)
#pragma unroll
        for (int r = 0; r < 2; ++r) {
            const int t0 = 4 * s + 2 * r;
            const float f00 = v0[t0], f01 = v0[t0 + 1];
            const float f10 = v1[t0], f11 = v1[t0 + 1];
            const uint32_t h0 = cvt_bf16x2(f01, f00);
            const uint32_t h1 = cvt_bf16x2(f11, f10);
            AH[s][2 * r]     = h0;
            AH[s][2 * r + 1] = h1;
            const float l00 = f00 - __uint_as_float(h0 << 16);
            const float l01 = f01 - __uint_as_float(h0 & 0xffff0000u);
            const float l10 = f10 - __uint_as_float(h1 << 16);
            const float l11 = f11 - __uint_as_float(h1 & 0xffff0000u);
            AL[s][2 * r]     = cvt_bf16x2(l01, l00);
            AL[s][2 * r + 1] = cvt_bf16x2(l11, l10);
        }

        // ---- prefetch next iteration's gathers (overlap with MMAs) ----
        if (it + 1 < ITERS)
            gather_taps(in_n, pbase + (it + 1) * 64, c, coff, dy, dx, v0, v1);

        // ---- 48 MMAs; BL reloaded from smem per (nt,s) ----
        float acc[8][4];
#pragma unroll
        for (int nt = 0; nt < 8; ++nt) {
            acc[nt][0] = 0.f; acc[nt][1] = 0.f; acc[nt][2] = 0.f; acc[nt][3] = 0.f;
        }
#pragma unroll
        for (int nt = 0; nt < 8; ++nt) {
            const uint2 bl0 = s_bl[(nt * 2 + 0) * 32 + lane];
            const uint2 bl1 = s_bl[(nt * 2 + 1) * 32 + lane];
            mma_bf16(acc[nt], AH[0], BH[nt][0]);
            mma_bf16(acc[nt], AH[0], &bl0.x);
            mma_bf16(acc[nt], AL[0], BH[nt][0]);
            mma_bf16(acc[nt], AH[1], BH[nt][1]);
            mma_bf16(acc[nt], AH[1], &bl1.x);
            mma_bf16(acc[nt], AL[1], BH[nt][1]);
        }

        // ---- store: per co, float2 of adjacent pixels (p0, p0+1) ----
        const int p0 = pbase + it * 64;   // even -> 8B aligned
#pragma unroll
        for (int nt = 0; nt < 8; ++nt) {
            const int co = nt * 8 + c;
            float* pl0 = out_n + (size_t)co * IMG + p0;
            float* pl1 = pl0 + IMG;
            *reinterpret_cast<float2*>(pl0) = make_float2(acc[nt][0], acc[nt][2]);
            *reinterpret_cast<float2*>(pl1) = make_float2(acc[nt][1], acc[nt][3]);
        }
    }
}

extern "C" void kernel_launch(void* const* d_in, const int* in_sizes, int n_in,
                              void* d_out, int out_size)
{
    const float* x = (const float*)d_in[0];
    const float* w = (const float*)d_in[1];
    const float* b = (const float*)d_in[2];
    float* out = (float*)d_out;

    dim3 block(NTHREADS, 1, 1);
    dim3 grid(NN * BLKS_PER_IMG, 1, 1);   // 3136
    conv_mma<<<grid, block>>>(x, w, b, out);
}

// round 11
// speedup vs baseline: 1.0634x; 1.0634x over previous
#include <cuda_runtime.h>
#include <cstdint>

// Conv2d N=32, CIN=3, H=W=224, COUT=64, 3x3, s1, p1, fp32.
// Implicit GEMM via mma.sync.m16n8k16 bf16->f32, 3-pass hi/lo fp32 emulation.
// R11: warp-cooperative input path. Each warp owns a row-aligned 16-px segment
// and walks 8 consecutive rows. Input patch (3ch x 3rows x 18cols) lives in
// registers, loaded coalesced (3 new rows/iter, software-pipelined) and
// distributed to MMA fragments via __shfl_sync (no L1 wavefronts).
// Edge zeros are load-time lane predicates. MMA/stores identical to R9.

#define HWDIM 224
#define IMG (HWDIM*HWDIM)        // 50176
#define COUT 64
#define CIN 3
#define NTHREADS 128

__device__ __forceinline__ uint32_t cvt_bf16x2(float hi, float lo) {
    uint32_t d;
    asm("cvt.rn.bf16x2.f32 %0, %1, %2;" : "=r"(d) : "f"(hi), "f"(lo));
    return d;
}
__device__ __forceinline__ void mma_bf16(float* d, const uint32_t* a, const uint32_t* b) {
    asm volatile(
        "mma.sync.aligned.m16n8k16.row.col.f32.bf16.bf16.f32 "
        "{%0,%1,%2,%3}, {%4,%5,%6,%7}, {%8,%9}, {%0,%1,%2,%3};"
        : "+f"(d[0]), "+f"(d[1]), "+f"(d[2]), "+f"(d[3])
        : "r"(a[0]), "r"(a[1]), "r"(a[2]), "r"(a[3]), "r"(b[0]), "r"(b[1]));
}

__global__ __launch_bounds__(NTHREADS, 3)
void conv_mma(const float* __restrict__ xin, const float* __restrict__ wgt,
              const float* __restrict__ bias, float* __restrict__ out)
{
    const int tid  = threadIdx.x;
    const int warp = tid >> 5;
    const int lane = tid & 31;
    const int lg   = lane >> 2;     // pixel-pair index 0..7
    const int cc   = (lane & 3) * 2;

    // grid: 32 imgs x 7 rowgroups x 14 x-segments
    const int b   = blockIdx.x;
    const int n   = b / 98;
    const int rem = b % 98;
    const int rg  = rem / 14;
    const int xc  = rem % 14;
    const float* in_n  = xin + (size_t)n * (CIN * IMG);
    float*       out_n = out + (size_t)n * (COUT * IMG);
    const int x0    = xc * 16;
    const int ybase = rg * 32 + warp * 8;

    // ---- B (weight+bias) fragments, hi/lo, built once per thread ----
    uint32_t BH[8][2][2], BL[8][2][2];
#pragma unroll
    for (int nt = 0; nt < 8; ++nt) {
        const int co = nt * 8 + lg;
#pragma unroll
        for (int s = 0; s < 2; ++s)
#pragma unroll
        for (int r = 0; r < 2; ++r) {
            const int k0 = 16 * s + cc + 8 * r;
            const int k1 = k0 + 1;
            const float f0 = (k0 < 27) ? wgt[co * 27 + k0] : (k0 == 27 ? bias[co] : 0.f);
            const float f1 = (k1 < 27) ? wgt[co * 27 + k1] : (k1 == 27 ? bias[co] : 0.f);
            const uint32_t h = cvt_bf16x2(f1, f0);
            const float l0 = f0 - __uint_as_float(h << 16);
            const float l1 = f1 - __uint_as_float(h & 0xffff0000u);
            BH[nt][s][r] = h;
            BL[nt][s][r] = cvt_bf16x2(l1, l0);
        }
    }

    // ---- patch loading setup: lane u holds x = x0 - 1 + u (u = 0..17) ----
    const bool lane_ok = (lane < 18)
                      && !(xc == 0  && lane == 0)     // x = -1
                      && !(xc == 13 && lane == 17);   // x = 224
    const float* rp = in_n + x0 - 1 + lane;           // + ci*IMG + yy*HWDIM

    // ---- prologue: patch rows for iteration 0 ----
    float P[3][3];   // P[ci][j] = row (ybase - 1 + j)
#pragma unroll
    for (int j = 0; j < 3; ++j) {
        const int yy  = ybase - 1 + j;
        const bool ok = lane_ok && ((unsigned)yy < (unsigned)HWDIM);
#pragma unroll
        for (int ci = 0; ci < CIN; ++ci)
            P[ci][j] = ok ? __ldg(rp + ci * IMG + yy * HWDIM) : 0.f;
    }

    for (int it = 0; it < 8; ++it) {
        const int y = ybase + it;

        // ---- distribute patch -> per-thread taps via shuffles ----
        // tap t of group c corresponds to k = c + {0,1,8,9,16,17,24,25}[t].
        // For k: owner c_k = k&6, slot t_k = 2*(k>>3)+(k&1).
        float v0[8], v1[8];
#pragma unroll
        for (int t = 0; t < 8; ++t) {
            const float d = (t == 7 && cc == 2) ? 1.f : 0.f;  // k=27 bias tap
            v0[t] = d; v1[t] = d;
        }
#pragma unroll
        for (int k = 0; k < 27; ++k) {
            const int ci = k / 9, r9 = k % 9, ky = r9 / 3, kx = r9 % 3;
            const float s0 = __shfl_sync(0xffffffffu, P[ci][ky], 2 * lg + kx);
            const float s1 = __shfl_sync(0xffffffffu, P[ci][ky], 2 * lg + kx + 1);
            const int ck = k & 6;
            const int t  = 2 * (k >> 3) + (k & 1);
            if (cc == ck) { v0[t] = s0; v1[t] = s1; }
        }

        // ---- split hi/lo, pack A fragments ----
        uint32_t AH[2][4], AL[2][4];
#pragma unroll
        for (int s = 0; s < 2; ++s)
#pragma unroll
        for (int r = 0; r < 2; ++r) {
            const int t0 = 4 * s + 2 * r;
            const float f00 = v0[t0], f01 = v0[t0 + 1];
            const float f10 = v1[t0], f11 = v1[t0 + 1];
            const uint32_t h0 = cvt_bf16x2(f01, f00);
            const uint32_t h1 = cvt_bf16x2(f11, f10);
            AH[s][2 * r]     = h0;
            AH[s][2 * r + 1] = h1;
            const float l00 = f00 - __uint_as_float(h0 << 16);
            const float l01 = f01 - __uint_as_float(h0 & 0xffff0000u);
            const float l10 = f10 - __uint_as_float(h1 << 16);
            const float l11 = f11 - __uint_as_float(h1 & 0xffff0000u);
            AL[s][2 * r]     = cvt_bf16x2(l01, l00);
            AL[s][2 * r + 1] = cvt_bf16x2(l11, l10);
        }

        // ---- prefetch next patch row (y+2), overlaps with MMAs ----
        float T[3];
        {
            const int yy  = y + 2;
            const bool ok = lane_ok && ((unsigned)yy < (unsigned)HWDIM);
#pragma unroll
            for (int ci = 0; ci < CIN; ++ci)
                T[ci] = ok ? __ldg(rp + ci * IMG + yy * HWDIM) : 0.f;
        }

        // ---- 48 MMAs ----
        float acc[8][4];
#pragma unroll
        for (int nt = 0; nt < 8; ++nt) {
            acc[nt][0] = 0.f; acc[nt][1] = 0.f; acc[nt][2] = 0.f; acc[nt][3] = 0.f;
        }
#pragma unroll
        for (int nt = 0; nt < 8; ++nt) {
#pragma unroll
            for (int s = 0; s < 2; ++s) {
                mma_bf16(acc[nt], AH[s], BH[nt][s]);
                mma_bf16(acc[nt], AH[s], BL[nt][s]);
                mma_bf16(acc[nt], AL[s], BH[nt][s]);
            }
        }

        // ---- store: per co, float2 of adjacent pixels (p0, p0+1) ----
        const int p0 = y * HWDIM + x0 + 2 * lg;   // even -> 8B aligned
#pragma unroll
        for (int nt = 0; nt < 8; ++nt) {
            const int co = nt * 8 + cc;
            float* pl0 = out_n + (size_t)co * IMG + p0;
            float* pl1 = pl0 + IMG;
            *reinterpret_cast<float2*>(pl0) = make_float2(acc[nt][0], acc[nt][2]);
            *reinterpret_cast<float2*>(pl1) = make_float2(acc[nt][1], acc[nt][3]);
        }

        // ---- rotate patch rows ----
#pragma unroll
        for (int ci = 0; ci < CIN; ++ci) {
            P[ci][0] = P[ci][1];
            P[ci][1] = P[ci][2];
            P[ci][2] = T[ci];
        }
    }
}

extern "C" void kernel_launch(void* const* d_in, const int* in_sizes, int n_in,
                              void* d_out, int out_size)
{
    const float* x = (const float*)d_in[0];
    const float* w = (const float*)d_in[1];
    const float* b = (const float*)d_in[2];
    float* out = (float*)d_out;

    dim3 block(NTHREADS, 1, 1);
    dim3 grid(32 * 7 * 14, 1, 1);   // 3136 blocks
    conv_mma<<<grid, block>>>(x, w, b, out);
}